// round 12
// baseline (speedup 1.0000x reference)
#include <cuda_runtime.h>
#include <cuda_bf16.h>
#include <cstdint>

// Sparsemax over rows of [B=2048, V=32000] fp32.
// 2-CTA clusters, one ROW per cluster, half-row per CTA held in registers
// (512 thr x 8 float4). 2 CTAs/SM (different clusters) => two independent
// row pipelines per SM: one CTA's serial phase (reduce/exchange/Michelot)
// is covered by the other's load/store streaming. Single pass, minimal
// 524MB traffic. Cross-CTA combine: candidates+max exchanged via DSMEM
// (mapa + st.shared::cluster), one barrier.cluster per row; Michelot runs
// redundantly in both CTAs over the rank-ordered union -> bit-identical tau.

#define THREADS  512
#define NWARP    16
#define VROW     32000
#define HALF_F4  4000          // float4 per half-row
#define TAIL_T   (HALF_F4 - 7 * THREADS)   // 416 valid threads in last iter
#define CAP_H    256           // per-half candidate cap
#define NEG_INF  (-3.4e38f)
#define SLACK    1.0009f

__device__ __forceinline__ uint32_t smem_addr(const void* p) {
    return (uint32_t)__cvta_generic_to_shared(p);
}
__device__ __forceinline__ uint32_t peer_addr(const void* p, uint32_t peer_rank) {
    uint32_t l = smem_addr(p), r;
    asm("mapa.shared::cluster.u32 %0, %1, %2;" : "=r"(r) : "r"(l), "r"(peer_rank));
    return r;
}
__device__ __forceinline__ void st_cluster_f32(uint32_t a, float v) {
    asm volatile("st.shared::cluster.f32 [%0], %1;" :: "r"(a), "f"(v) : "memory");
}
__device__ __forceinline__ void st_cluster_u32(uint32_t a, unsigned v) {
    asm volatile("st.shared::cluster.u32 [%0], %1;" :: "r"(a), "r"(v) : "memory");
}
__device__ __forceinline__ void cluster_sync() {
    asm volatile("barrier.cluster.arrive.aligned;" ::: "memory");
    asm volatile("barrier.cluster.wait.aligned;" ::: "memory");
}

__global__ __launch_bounds__(THREADS, 2) __cluster_dims__(2, 1, 1)
void sparsemax_kernel(const float* __restrict__ in, float* __restrict__ out, int B)
{
    __shared__ float cbuf[2][2][CAP_H];   // [parity][rank][slot]
    __shared__ int   cnum[2][2];          // [parity][rank]
    __shared__ float cmax[2][2];          // [parity][rank]
    __shared__ float s_red[NWARP];

    const int tid  = threadIdx.x;
    const int lane = tid & 31;
    const int wid  = tid >> 5;
    const unsigned FULL = 0xffffffffu;

    const int rank  = (int)(blockIdx.x & 1);      // rank within 2-CTA cluster
    const int prank = rank ^ 1;
    const int cl    = (int)(blockIdx.x >> 1);     // cluster id
    const int NC    = (int)(gridDim.x >> 1);

    if (tid == 0) {
        cnum[0][0] = 0; cnum[0][1] = 0;
        cnum[1][0] = 0; cnum[1][1] = 0;
    }
    __syncthreads();
    cluster_sync();          // peer must not see uninitialized cnum

    int lr = 0;
    for (int row = cl; row < B; row += NC, ++lr) {
        const int p = lr & 1;

        // ---- load my half-row into registers, fused max scan ----
        const float4* hb = (const float4*)(in + (size_t)row * VROW) + rank * HALF_F4;
        float4 v[8];
        float tm = NEG_INF;
#pragma unroll
        for (int i = 0; i < 7; ++i) {
            v[i] = __ldcs(&hb[tid + i * THREADS]);
            tm = fmaxf(tm, fmaxf(fmaxf(v[i].x, v[i].y), fmaxf(v[i].z, v[i].w)));
        }
        if (tid < TAIL_T) {
            v[7] = __ldcs(&hb[tid + 7 * THREADS]);
            tm = fmaxf(tm, fmaxf(fmaxf(v[7].x, v[7].y), fmaxf(v[7].z, v[7].w)));
        } else {
            v[7] = make_float4(NEG_INF, NEG_INF, NEG_INF, NEG_INF);
        }

        // ---- block max of my half ----
#pragma unroll
        for (int o = 16; o; o >>= 1)
            tm = fmaxf(tm, __shfl_xor_sync(FULL, tm, o));
        if (lane == 0) s_red[wid] = tm;
        __syncthreads();
        if (wid == 0) {
            float m = (lane < NWARP) ? s_red[lane] : NEG_INF;
#pragma unroll
            for (int o = 8; o; o >>= 1)
                m = fmaxf(m, __shfl_xor_sync(FULL, m, o));
            if (lane == 0) cmax[p][rank] = m;
        }
        __syncthreads();

        const float hmax = cmax[p][rank];
        const float th = hmax - SLACK;   // hmax <= rmax  =>  superset of support

        // ---- compact my half's candidates (count + one atomicAdd) ----
        int c = 0;
#pragma unroll
        for (int i = 0; i < 8; ++i)
            c += (v[i].x >= th) + (v[i].y >= th) + (v[i].z >= th) + (v[i].w >= th);
        if (c) {
            int base = atomicAdd(&cnum[p][rank], c);
#pragma unroll
            for (int i = 0; i < 8; ++i) {
                float a4[4] = {v[i].x, v[i].y, v[i].z, v[i].w};
#pragma unroll
                for (int e = 0; e < 4; ++e)
                    if (a4[e] >= th) { if (base < CAP_H) cbuf[p][rank][base] = a4[e]; ++base; }
            }
        }
        // reset other-parity counter BEFORE the cluster sync: peer's next-row
        // dsmem writes to cnum[p^1][prank] happen strictly after this sync.
        if (tid == 0) cnum[p ^ 1][rank] = 0;
        __syncthreads();                   // compaction complete

        // ---- exchange my half's {cand, num, max} into peer smem ----
        const int myn = cnum[p][rank];
        const int cpy = myn < CAP_H ? myn : CAP_H;
        for (int j = tid; j < cpy; j += THREADS)
            st_cluster_f32(peer_addr(&cbuf[p][rank][j], prank), cbuf[p][rank][j]);
        if (tid == 0) {
            st_cluster_u32(peer_addr(&cnum[p][rank], prank), (unsigned)myn);
            st_cluster_f32(peer_addr(&cmax[p][rank], prank), cmax[p][rank]);
        }
        cluster_sync();                    // both halves visible in both CTAs

        // ---- combine + Michelot (redundant per warp; rank-ordered => same tau) ----
        const float rmax = fmaxf(cmax[p][0], cmax[p][1]);
        const int n0 = cnum[p][0];
        const int n1 = cnum[p][1];

        float t = -1.0f;   // shifted tau* in [-1, 0]; support is y > t
        if (n0 <= CAP_H && n1 <= CAP_H) {
            int prev = -1;
            const int tot = n0 + n1;
            for (int itc = 0; itc < tot + 2; ++itc) {
                float sum = 0.0f; int cnt = 0;
                for (int i = lane; i < n0; i += 32) {
                    float y = cbuf[p][0][i] - rmax;
                    if (y > t) { sum += y; cnt++; }
                }
                for (int i = lane; i < n1; i += 32) {
                    float y = cbuf[p][1][i] - rmax;
                    if (y > t) { sum += y; cnt++; }
                }
#pragma unroll
                for (int o = 16; o; o >>= 1) {
                    sum += __shfl_xor_sync(FULL, sum, o);
                    cnt += __shfl_xor_sync(FULL, cnt, o);
                }
                if (cnt == prev) break;    // fixed point -> exact tau
                prev = cnt;
                t = (sum - 1.0f) / (float)cnt;
            }
        } else {
            // overflow fallback (degenerate inputs only): exact Michelot over
            // the FULL row from global memory (deterministic, same in both CTAs).
            const float* rp = in + (size_t)row * VROW;
            t = -2.0f;
            int prev = -1;
            for (int itc = 0; itc < VROW; ++itc) {
                float sum = 0.0f; int cnt = 0;
                for (int i = lane; i < VROW; i += 32) {
                    float y = __ldg(&rp[i]) - rmax;
                    if (y > t) { sum += y; cnt++; }
                }
#pragma unroll
                for (int o = 16; o; o >>= 1) {
                    sum += __shfl_xor_sync(FULL, sum, o);
                    cnt += __shfl_xor_sync(FULL, cnt, o);
                }
                if (cnt == prev) break;
                prev = cnt;
                t = (sum - 1.0f) / (float)cnt;
            }
        }
        const float tau = rmax + t;

        // ---- store my half from registers ----
        float4* ob = (float4*)(out + (size_t)row * VROW) + rank * HALF_F4;
#pragma unroll
        for (int i = 0; i < 7; ++i) {
            float4 r;
            r.x = fmaxf(v[i].x - tau, 0.0f);
            r.y = fmaxf(v[i].y - tau, 0.0f);
            r.z = fmaxf(v[i].z - tau, 0.0f);
            r.w = fmaxf(v[i].w - tau, 0.0f);
            __stcs(&ob[tid + i * THREADS], r);
        }
        if (tid < TAIL_T) {
            float4 r;
            r.x = fmaxf(v[7].x - tau, 0.0f);
            r.y = fmaxf(v[7].y - tau, 0.0f);
            r.z = fmaxf(v[7].z - tau, 0.0f);
            r.w = fmaxf(v[7].w - tau, 0.0f);
            __stcs(&ob[tid + 7 * THREADS], r);
        }
    }
}

extern "C" void kernel_launch(void* const* d_in, const int* in_sizes, int n_in,
                              void* d_out, int out_size)
{
    const float* in = (const float*)d_in[0];
    float* out = (float*)d_out;
    const int B = out_size / VROW;

    int sms = 148;
    cudaDeviceGetAttribute(&sms, cudaDevAttrMultiProcessorCount, 0);
    int G = 2 * sms;                 // 152 clusters of 2 CTAs, 2 CTAs/SM
    if (G > 2 * B) G = 2 * B;        // at most one cluster per row

    sparsemax_kernel<<<G, THREADS>>>(in, out, B);
}

// round 13
// speedup vs baseline: 1.2824x; 1.2824x over previous
#include <cuda_runtime.h>
#include <cuda_bf16.h>
#include <cstdint>

// Sparsemax over rows of [B=2048, V=32000] fp32.
// Persistent CTAs (1/SM, 1024 thr). cp.async.bulk (TMA) drives reads into a
// 7-slot x 32KB smem ring (lookahead staggered 7/6/5 by bid%3). Per row:
//   capture smem->regs (fused warp max, keep PER-THREAD max) ->
//   block max via 32-bit atomicMax(monotone key) ->
//   compaction with per-thread-max EARLY-OUT (97% of threads do 1 compare) ->
//   redundant per-warp Michelot with n<=32 register fast path (exact tau) ->
//   register store pass (__stcs). Refill: 4 chunks at sync A, constant
//   lookahead invariant rlim = depth + (lr+1)*NCHUNK.

#define THREADS     1024
#define VROW        32000
#define NCHUNK      4
#define CHUNK_BYTES 32000
#define CHUNK_F4    2000
#define NSLOT       7
#define CAP         512
#define NEG_INF     (-3.4e38f)
#define SLACK       1.0009f

// dynamic smem layout (bytes)
#define OFF_BUF    0
#define OFF_CAND   (NSLOT * CHUNK_BYTES)          // 224000
#define OFF_NUM    (OFF_CAND + 2 * CAP * 4)       // 228096
#define OFF_MAXB   (OFF_NUM + 8)                  // 228104
#define OFF_MBAR   (OFF_MAXB + 8)                 // 228112 (8-aligned)
#define SMEM_TOTAL (OFF_MBAR + NSLOT * 8)         // 228168

__device__ __forceinline__ uint32_t smem_u32(const void* p) {
    return (uint32_t)__cvta_generic_to_shared(p);
}
__device__ __forceinline__ void mbar_init(uint32_t a, uint32_t cnt) {
    asm volatile("mbarrier.init.shared.b64 [%0], %1;" :: "r"(a), "r"(cnt) : "memory");
}
__device__ __forceinline__ void mbar_expect_tx(uint32_t a, uint32_t tx) {
    asm volatile("mbarrier.arrive.expect_tx.shared.b64 _, [%0], %1;"
                 :: "r"(a), "r"(tx) : "memory");
}
__device__ __forceinline__ void mbar_wait(uint32_t a, uint32_t parity) {
    asm volatile(
        "{\n\t"
        ".reg .pred P1;\n\t"
        "WAIT_LOOP_%=:\n\t"
        "mbarrier.try_wait.parity.acquire.cta.shared::cta.b64 P1, [%0], %1, 0x989680;\n\t"
        "@P1 bra.uni WAIT_DONE_%=;\n\t"
        "bra.uni WAIT_LOOP_%=;\n\t"
        "WAIT_DONE_%=:\n\t"
        "}"
        :: "r"(a), "r"(parity) : "memory");
}
__device__ __forceinline__ void bulk_g2s(uint32_t dst, const void* src,
                                         uint32_t bytes, uint32_t mbar) {
    asm volatile(
        "cp.async.bulk.shared::cta.global.mbarrier::complete_tx::bytes [%0], [%1], %2, [%3];"
        :: "r"(dst), "l"(src), "r"(bytes), "r"(mbar) : "memory");
}
__device__ __forceinline__ void fence_proxy_async() {
    asm volatile("fence.proxy.async;" ::: "memory");
}

// monotone float<->uint key: order-preserving for all finite floats
__device__ __forceinline__ unsigned fkey(float x) {
    unsigned u = __float_as_uint(x);
    return (u & 0x80000000u) ? ~u : (u | 0x80000000u);
}
__device__ __forceinline__ float funkey(unsigned k) {
    unsigned u = (k & 0x80000000u) ? (k ^ 0x80000000u) : ~k;
    return __uint_as_float(u);
}

__global__ __launch_bounds__(THREADS, 1)
void sparsemax_kernel(const float* __restrict__ in, float* __restrict__ out, int B)
{
    extern __shared__ char smem[];
    float*    cand   = (float*)(smem + OFF_CAND);       // [2][CAP]
    int*      s_num  = (int*)(smem + OFF_NUM);          // [2]
    unsigned* s_maxb = (unsigned*)(smem + OFF_MAXB);    // [2]
    const uint32_t mb = smem_u32(smem + OFF_MBAR);

    const int tid  = threadIdx.x;
    const int lane = tid & 31;
    const int bid  = blockIdx.x;
    const int G    = gridDim.x;
    const unsigned FULL = 0xffffffffu;

    if (bid >= B) return;

    const int nrows = (B - bid + G - 1) / G;
    const int Q = NCHUNK * nrows;

    if (tid == 0) {
        s_num[0] = 0;  s_num[1] = 0;
        s_maxb[0] = 0; s_maxb[1] = 0;
        for (int s = 0; s < NSLOT; ++s) mbar_init(mb + s * 8, 1);
        fence_proxy_async();
    }
    __syncthreads();

    // ---- prime the ring (lookahead staggered by bid to de-phase CTAs) ----
    int qi = 0;
    const int depth = NSLOT - (bid % 3);     // 7 / 6 / 5, all > NCHUNK
    if (tid == 0) {
        int lim = Q < depth ? Q : depth;
        for (; qi < lim; ++qi) {
            int lr2 = qi >> 2, ck = qi & 3;
            const char* src = (const char*)(in + (size_t)(bid + lr2 * G) * VROW)
                              + (size_t)ck * CHUNK_BYTES;
            uint32_t m = mb + (qi % NSLOT) * 8;
            mbar_expect_tx(m, CHUNK_BYTES);
            bulk_g2s(smem_u32(smem + OFF_BUF + (qi % NSLOT) * CHUNK_BYTES),
                     src, CHUNK_BYTES, m);
        }
    }

    for (int lr = 0; lr < nrows; ++lr) {
        const int row = bid + lr * G;
        const int p   = lr & 1;                 // parity buffer for this row
        float*    cbuf = cand + p * CAP;
        // issue quota: keep constant lookahead == depth (safe: chunk q's slot
        // last held q-7, whose row <= lr is captured before this refill point)
        int rlim = depth + (lr + 1) * NCHUNK;
        if (rlim > Q) rlim = Q;

        // ---- capture row smem -> regs, fused max scan ----
        float4 v[8];
        float tm = NEG_INF;
#pragma unroll
        for (int k = 0; k < NCHUNK; ++k) {
            const int q = lr * NCHUNK + k;
            const int slot = q % NSLOT;
            mbar_wait(mb + slot * 8, (q / NSLOT) & 1);
            const float4* cb = (const float4*)(smem + OFF_BUF + slot * CHUNK_BYTES);
            v[2 * k] = cb[tid];
            tm = fmaxf(tm, fmaxf(fmaxf(v[2*k].x, v[2*k].y), fmaxf(v[2*k].z, v[2*k].w)));
            if (tid < CHUNK_F4 - THREADS) {     // tid < 976
                v[2 * k + 1] = cb[tid + THREADS];
                tm = fmaxf(tm, fmaxf(fmaxf(v[2*k+1].x, v[2*k+1].y),
                                     fmaxf(v[2*k+1].z, v[2*k+1].w)));
            } else {
                v[2 * k + 1] = make_float4(NEG_INF, NEG_INF, NEG_INF, NEG_INF);
            }
        }
        const float tmt = tm;                    // PER-THREAD max (pre-shuffle)

        // ---- block max: warp reduce + one 32-bit atomicMax per warp ----
#pragma unroll
        for (int o = 16; o; o >>= 1)
            tm = fmaxf(tm, __shfl_xor_sync(FULL, tm, o));
        if (lane == 0) atomicMax(&s_maxb[p], fkey(tm));
        __syncthreads();                         // sync A: max done, captures done

        const float rmax = funkey(s_maxb[p]);
        const float th = rmax - SLACK;           // tau* >= rmax-1 => superset

        // tid0: reset other-parity state for NEXT row; refill this row's quota
        if (tid == 0) {
            s_num[p ^ 1] = 0;
            s_maxb[p ^ 1] = 0;
            for (; qi < rlim; ++qi) {
                int ilr = qi >> 2, ck = qi & 3;
                const char* src = (const char*)(in + (size_t)(bid + ilr * G) * VROW)
                                  + (size_t)ck * CHUNK_BYTES;
                uint32_t mm = mb + (qi % NSLOT) * 8;
                mbar_expect_tx(mm, CHUNK_BYTES);
                bulk_g2s(smem_u32(smem + OFF_BUF + (qi % NSLOT) * CHUNK_BYTES),
                         src, CHUNK_BYTES, mm);
            }
        }

        // ---- compaction with per-thread-max early-out (rare path ~3%) ----
        if (tmt >= th) {
            int c = 0;
#pragma unroll
            for (int i = 0; i < 8; ++i)
                c += (v[i].x >= th) + (v[i].y >= th) + (v[i].z >= th) + (v[i].w >= th);
            int base = atomicAdd(&s_num[p], c);
#pragma unroll
            for (int i = 0; i < 8; ++i) {
                float a4[4] = {v[i].x, v[i].y, v[i].z, v[i].w};
#pragma unroll
                for (int e = 0; e < 4; ++e)
                    if (a4[e] >= th) { if (base < CAP) cbuf[base] = a4[e]; ++base; }
            }
        }
        __syncthreads();                         // sync B: candidates complete

        // ---- Michelot, redundantly in EVERY warp (no barrier after) ----
        const int n = s_num[p];
        float t = -1.0f;    // tau* >= -1 (shifted); support is y > tau*
        if (n <= 32) {
            // register fast path: lane holds one candidate; no memory in iters
            float y = (lane < n) ? (cbuf[lane] - rmax) : -2.0f;
            int prev = -1;
            for (int itc = 0; itc < n + 2; ++itc) {
                bool act = (y > t);
                unsigned m = __ballot_sync(FULL, act);
                int cnt = __popc(m);
                float sum = act ? y : 0.0f;
#pragma unroll
                for (int o = 16; o; o >>= 1)
                    sum += __shfl_xor_sync(FULL, sum, o);
                if (cnt == prev) break;          // fixed point -> exact tau
                prev = cnt;
                t = (sum - 1.0f) / (float)cnt;
            }
        } else if (n <= CAP) {
            int prev = -1;
            for (int itc = 0; itc < n + 2; ++itc) {
                float sum = 0.0f; int cnt = 0;
                for (int i = lane; i < n; i += 32) {
                    float y = cbuf[i] - rmax;
                    if (y > t) { sum += y; cnt++; }
                }
#pragma unroll
                for (int o = 16; o; o >>= 1) {
                    sum += __shfl_xor_sync(FULL, sum, o);
                    cnt += __shfl_xor_sync(FULL, cnt, o);
                }
                if (cnt == prev) break;
                prev = cnt;
                t = (sum - 1.0f) / (float)cnt;
            }
        } else {
            // overflow fallback (degenerate inputs only): exact Michelot over
            // the full row from global memory, redundantly per warp.
            const float* rp = in + (size_t)row * VROW;
            t = -2.0f;
            int prev = -1;
            for (int itc = 0; itc < VROW; ++itc) {
                float sum = 0.0f; int cnt = 0;
                for (int i = lane; i < VROW; i += 32) {
                    float y = __ldg(&rp[i]) - rmax;
                    if (y > t) { sum += y; cnt++; }
                }
#pragma unroll
                for (int o = 16; o; o >>= 1) {
                    sum += __shfl_xor_sync(FULL, sum, o);
                    cnt += __shfl_xor_sync(FULL, cnt, o);
                }
                if (cnt == prev) break;
                prev = cnt;
                t = (sum - 1.0f) / (float)cnt;
            }
        }
        const float tau = rmax + t;

        // ---- store row from registers (TMA keeps filling behind this) ----
        float4* orow = (float4*)(out + (size_t)row * VROW);
#pragma unroll
        for (int k = 0; k < NCHUNK; ++k) {
            int idx = k * CHUNK_F4 + tid;
            float4 r;
            r.x = fmaxf(v[2*k].x - tau, 0.0f);
            r.y = fmaxf(v[2*k].y - tau, 0.0f);
            r.z = fmaxf(v[2*k].z - tau, 0.0f);
            r.w = fmaxf(v[2*k].w - tau, 0.0f);
            __stcs(&orow[idx], r);
            if (tid < CHUNK_F4 - THREADS) {
                float4 r2;
                r2.x = fmaxf(v[2*k+1].x - tau, 0.0f);
                r2.y = fmaxf(v[2*k+1].y - tau, 0.0f);
                r2.z = fmaxf(v[2*k+1].z - tau, 0.0f);
                r2.w = fmaxf(v[2*k+1].w - tau, 0.0f);
                __stcs(&orow[idx + THREADS], r2);
            }
        }
    }
}

extern "C" void kernel_launch(void* const* d_in, const int* in_sizes, int n_in,
                              void* d_out, int out_size)
{
    const float* in = (const float*)d_in[0];
    float* out = (float*)d_out;
    const int B = out_size / VROW;

    int sms = 148;
    cudaDeviceGetAttribute(&sms, cudaDevAttrMultiProcessorCount, 0);
    int G = sms;
    if (G > B) G = B;

    cudaFuncSetAttribute(sparsemax_kernel,
                         cudaFuncAttributeMaxDynamicSharedMemorySize, SMEM_TOTAL);
    sparsemax_kernel<<<G, THREADS, SMEM_TOTAL>>>(in, out, B);
}